// round 14
// baseline (speedup 1.0000x reference)
#include <cuda_runtime.h>
#include <cuda_fp16.h>
#include <cstdint>

#define NB   12544
#define MTOT 2048
#define DDIM 256

typedef __half h16;

// ---------------- scratch ----------------
__device__ __align__(16) h16 g_x[NB * DDIM];
__device__ __align__(16) h16 g_cm[MTOT * DDIM];
__device__ __align__(16) h16 g_sm2[MTOT * DDIM];
__device__ __align__(16) h16 g_w[6 * DDIM * DDIM];
__device__ __align__(16) h16 g_Qc[NB * DDIM];
__device__ __align__(16) h16 g_Qf[NB * DDIM];
__device__ __align__(16) h16 g_Kc[MTOT * DDIM];
__device__ __align__(16) h16 g_Kf[MTOT * DDIM];
__device__ __align__(16) h16 g_Vtc[DDIM * MTOT];
__device__ __align__(16) h16 g_Vtf[DDIM * MTOT];
__device__ __align__(16) h16 g_P0[(size_t)NB * MTOT];
__device__ __align__(16) h16 g_P1[(size_t)NB * MTOT];
__device__ float g_psum0[NB * 16], g_psum1[NB * 16];
__device__ float g_qm[NB], g_qv[NB], g_km[MTOT], g_kv[MTOT];

// ---------------- helpers ----------------
__device__ __forceinline__ uint32_t smem_u32(const void* p) {
    uint32_t a;
    asm("{ .reg .u64 t; cvta.to.shared.u64 t, %1; cvt.u32.u64 %0, t; }" : "=r"(a) : "l"(p));
    return a;
}
#define SWZ(o) ((o) ^ (((o) >> 3) & 0x70))

__device__ __forceinline__ void mma16816h(float* c, const uint32_t* a, const uint32_t* b) {
    asm volatile(
        "mma.sync.aligned.m16n8k16.row.col.f32.f16.f16.f32 "
        "{%0,%1,%2,%3}, {%4,%5,%6,%7}, {%8,%9}, {%0,%1,%2,%3};"
        : "+f"(c[0]), "+f"(c[1]), "+f"(c[2]), "+f"(c[3])
        : "r"(a[0]), "r"(a[1]), "r"(a[2]), "r"(a[3]), "r"(b[0]), "r"(b[1]));
}
__device__ __forceinline__ void ldsm_x4(uint32_t* r, uint32_t addr) {
    asm volatile("ldmatrix.sync.aligned.m8n8.x4.shared.b16 {%0,%1,%2,%3}, [%4];"
                 : "=r"(r[0]), "=r"(r[1]), "=r"(r[2]), "=r"(r[3]) : "r"(addr));
}
__device__ __forceinline__ void cp16(uint32_t dst, const void* src) {
    asm volatile("cp.async.cg.shared.global [%0], [%1], 16;" :: "r"(dst), "l"(src));
}
#define CP_COMMIT() asm volatile("cp.async.commit_group;" ::: "memory")
#define CP_WAIT1()  asm volatile("cp.async.wait_group 1;" ::: "memory")

// 32-K chunk packed tile: 128 rows x 64B -> 64 smem rows x 128B
__device__ __forceinline__ uint32_t toff32(int row, int cb) {
    return SWZ((uint32_t)((row & 63) * 128 + ((row >> 6) << 6) + cb));
}
// 64-K chunk full tile: 128 rows x 128B
__device__ __forceinline__ uint32_t toff64(int row, int cb) {
    return SWZ((uint32_t)(row * 128 + cb));
}

#define TILE_STG 32768
#define GEMM_SMEM (3 * TILE_STG)
#define PV_SMEM (3 * TILE_STG + 1024)
#define SC_STG 16384
#define SC_SMEM (3 * SC_STG)

// ---------------- fp32 -> fp16 conversion (9 arrays) ----------------
struct ConvArgs {
    const float* src[9];
    h16* dst[9];
    int nblk[9];
};
__global__ __launch_bounds__(256) void conv_all(ConvArgs a) {
    int bx = blockIdx.x, z = 0;
    while (bx >= a.nblk[z]) { bx -= a.nblk[z]; z++; }
    size_t i = ((size_t)bx * 256 + threadIdx.x) * 4;
    float4 v = *(const float4*)(a.src[z] + i);
    __half2 ha; ha.x = __float2half(v.x); ha.y = __float2half(v.y);
    __half2 hb; hb.x = __float2half(v.z); hb.y = __float2half(v.w);
    *(__half2*)(a.dst[z] + i) = ha;
    *(__half2*)(a.dst[z] + i + 2) = hb;
}

// ---------------- shared mainloop pieces ----------------
#define MMA_DECL()                                                              \
    float acc[2][8][4];                                                         \
    _Pragma("unroll")                                                           \
    for (int rf = 0; rf < 2; rf++)                                              \
        _Pragma("unroll")                                                       \
        for (int nt = 0; nt < 8; nt++)                                          \
            _Pragma("unroll")                                                   \
            for (int c = 0; c < 4; c++) acc[rf][nt][c] = 0.f;                   \
    const int a_row = wm * 32 + (lane & 15);                                    \
    const int a_kb  = (lane >> 4) * 16;                                         \
    const int b_row = wn * 64 + ((lane >> 4) << 3) + (lane & 7);                \
    const int b_kb  = ((lane >> 3) & 1) * 16;

// 64-K chunk run over operands Ap/Bp; accumulates into acc.
#define MMA_RUN64(Ap, Bp, KL) {                                                 \
    const h16* __restrict__ A_ = (Ap);                                          \
    const h16* __restrict__ B_ = (Bp);                                          \
    const int Klen_ = (KL);                                                     \
    const int nIter = Klen_ >> 6;                                               \
    auto issue = [&](int buf_, int k0) {                                        \
        uint32_t base = sb + buf_ * TILE_STG;                                   \
        _Pragma("unroll")                                                       \
        for (int u = 0; u < 4; u++) {                                           \
            int idx = u * 256 + tid;                                            \
            int r = idx >> 3, gch = idx & 7;                                    \
            uint32_t off = SWZ((uint32_t)(r * 128 + gch * 16));                 \
            cp16(base + off,         A_ + (size_t)(mBase + r) * Klen_ + k0 + gch * 8); \
            cp16(base + 16384 + off, B_ + (size_t)(nBase + r) * Klen_ + k0 + gch * 8); \
        }                                                                       \
    };                                                                          \
    issue(0, 0); CP_COMMIT();                                                   \
    if (nIter > 1) issue(1, 64);                                                \
    CP_COMMIT();                                                                \
    int buf = 0;                                                                \
    for (int it = 0; it < nIter; it++) {                                        \
        CP_WAIT1();                                                             \
        __syncthreads();                                                        \
        if (it + 2 < nIter) issue((it + 2) % 3, (it + 2) * 64);                 \
        CP_COMMIT();                                                            \
        const uint32_t sbase = sb + buf * TILE_STG;                             \
        _Pragma("unroll")                                                       \
        for (int ks = 0; ks < 4; ks++) {                                        \
            uint32_t ah[2][4];                                                  \
            _Pragma("unroll")                                                   \
            for (int rf = 0; rf < 2; rf++)                                      \
                ldsm_x4(ah[rf], sbase + toff64(a_row + rf * 16, ks * 32 + a_kb)); \
            _Pragma("unroll")                                                   \
            for (int ntp = 0; ntp < 4; ntp++) {                                 \
                uint32_t bh4[4];                                                \
                ldsm_x4(bh4, sbase + 16384 + toff64(b_row + ntp * 16, ks * 32 + b_kb)); \
                _Pragma("unroll")                                               \
                for (int rf = 0; rf < 2; rf++) {                                \
                    mma16816h(acc[rf][2 * ntp],     ah[rf], bh4);               \
                    mma16816h(acc[rf][2 * ntp + 1], ah[rf], bh4 + 2);           \
                }                                                               \
            }                                                                   \
        }                                                                       \
        buf++; if (buf == 3) buf = 0;                                           \
    }                                                                           \
}

// ---------------- projection GEMMs (single-product fp16, 64-K) ----------------
struct ProjM {
    const h16 *A_[6], *B_[6];
    h16* O[6];
    int mx[6], trans[6];
};
__global__ __launch_bounds__(256, 2) void mma_proj(ProjM p) {
    extern __shared__ char sm[];
    const int z = blockIdx.z;
    if ((int)blockIdx.x >= p.mx[z]) return;
    const uint32_t sb = smem_u32(sm);
    const int tid = threadIdx.x;
    const int wid = tid >> 5, lane = tid & 31;
    const int wm = wid & 3, wn = wid >> 2;
    const int mBase = blockIdx.x * 128;
    const int nBase = blockIdx.y * 128;

    MMA_DECL();
    MMA_RUN64(p.A_[z], p.B_[z], 256);

    const int gID = lane >> 2, tig = lane & 3;
    h16* __restrict__ O = p.O[z];
    __syncthreads();
    char* smP = sm;

    if (p.trans[z]) {
        // stage transposed [d_local(128)][m_local(128)] fp16, then coalesced STG
#pragma unroll
        for (int rf = 0; rf < 2; rf++) {
#pragma unroll
            for (int nt = 0; nt < 8; nt++) {
#pragma unroll
                for (int c = 0; c < 4; c++) {
                    int ml = wm * 32 + rf * 16 + (c >> 1) * 8 + gID;
                    int dl = wn * 64 + nt * 8 + tig * 2 + (c & 1);
                    uint32_t addr = dl * 256 + (((ml >> 3) ^ (dl & 15)) << 4) + (ml & 7) * 2;
                    *(h16*)(smP + addr) = __float2half(acc[rf][nt][c]);
                }
            }
        }
        __syncthreads();
#pragma unroll
        for (int it = 0; it < 8; it++) {
            int idx = it * 256 + tid;
            int d = idx >> 4, cch = idx & 15;
            uint32_t src = d * 256 + ((cch ^ (d & 15)) << 4);
            size_t dst = (size_t)(nBase + d) * MTOT + mBase + cch * 8;
            *(uint4*)(O + dst) = *(uint4*)(smP + src);
        }
        return;
    }

#pragma unroll
    for (int rf = 0; rf < 2; rf++) {
#pragma unroll
        for (int nt = 0; nt < 8; nt++) {
            int chunk = wn * 8 + nt;
#pragma unroll
            for (int half = 0; half < 2; half++) {
                int rl = wm * 32 + rf * 16 + half * 8 + gID;
                __half2 hh;
                hh.x = __float2half(acc[rf][nt][half * 2 + 0]);
                hh.y = __float2half(acc[rf][nt][half * 2 + 1]);
                uint32_t addr = rl * 256 + ((chunk ^ (rl & 15)) << 4) + tig * 4;
                *(__half2*)(smP + addr) = hh;
            }
        }
    }
    __syncthreads();
#pragma unroll
    for (int it = 0; it < 8; it++) {
        int idx = it * 256 + tid;
        int r = idx >> 4, c = idx & 15;
        uint32_t src = r * 256 + ((c ^ (r & 15)) << 4);
        size_t dst = (size_t)(mBase + r) * 256 + nBase + c * 8;
        *(uint4*)(O + dst) = *(uint4*)(smP + src);
    }
}

// ---------------- merged row stats (fp16 input) ----------------
__global__ __launch_bounds__(256) void row_stats2(
    const h16* __restrict__ Qf, const h16* __restrict__ Kf,
    float* __restrict__ qm, float* __restrict__ qv,
    float* __restrict__ km, float* __restrict__ kv) {
    int row = blockIdx.x * 8 + (threadIdx.x >> 5);
    const int lane = threadIdx.x & 31;
    const h16* X;
    float *mean, *var;
    if (row < NB) { X = Qf; mean = qm; var = qv; }
    else { row -= NB; X = Kf; mean = km; var = kv; }
    const size_t base = (size_t)row * 256;
    float s = 0.f, ss = 0.f;
#pragma unroll
    for (int c = 0; c < 256; c += 32) {
        float v = __half2float(X[base + c + lane]);
        s += v; ss += v * v;
    }
#pragma unroll
    for (int o = 16; o > 0; o >>= 1) {
        s += __shfl_xor_sync(0xffffffffu, s, o);
        ss += __shfl_xor_sync(0xffffffffu, ss, o);
    }
    if (lane == 0) {
        float m = s * (1.f / 256.f);
        mean[row] = m;
        var[row] = (ss - 256.f * m * m) * (1.f / 255.f);
    }
}

// ---------------- score MMA GEMM: single-product fp16, 32-K chunks ----------------
struct MMArgs {
    const h16 *A_[2], *B_[2];
    h16* P[2];
    float* psum[2];
    const float *qm, *qv, *km, *kv;
};

__global__ __launch_bounds__(256, 2) void mma_gemm(MMArgs g) {
    extern __shared__ char sm[];
    const uint32_t sb = smem_u32(sm);
    const int z = blockIdx.z;
    const h16* __restrict__ A = g.A_[z];
    const h16* __restrict__ B = g.B_[z];
    const int Klen = 256;
    const int tid = threadIdx.x;
    const int wid = tid >> 5, lane = tid & 31;
    const int wm = wid & 3, wn = wid >> 2;
    const int mBase = blockIdx.x * 128;
    const int nBase = blockIdx.y * 128;

    float acc[2][8][4];
#pragma unroll
    for (int rf = 0; rf < 2; rf++)
#pragma unroll
        for (int nt = 0; nt < 8; nt++)
#pragma unroll
            for (int c = 0; c < 4; c++) acc[rf][nt][c] = 0.f;

    const int a_row = wm * 32 + (lane & 15);
    const int a_kb  = (lane >> 4) * 16;
    const int b_row = wn * 64 + ((lane >> 4) << 3) + (lane & 7);
    const int b_kb  = ((lane >> 3) & 1) * 16;
    const int lr0 = tid >> 2;
    const int lg  = (tid & 3);
    const int nIter = Klen >> 5;

    auto issue = [&](int buf, int k0) {
        uint32_t base = sb + buf * SC_STG;
#pragma unroll
        for (int h = 0; h < 2; h++) {
            int r = lr0 + h * 64;
            uint32_t off = toff32(r, lg * 16);
            cp16(base + off,        A + (size_t)(mBase + r) * Klen + k0 + lg * 8);
            cp16(base + 8192 + off, B + (size_t)(nBase + r) * Klen + k0 + lg * 8);
        }
    };

    issue(0, 0); CP_COMMIT();
    issue(1, 32); CP_COMMIT();

    int buf = 0;
    for (int it = 0; it < nIter; it++) {
        CP_WAIT1();
        __syncthreads();
        if (it + 2 < nIter) issue((it + 2) % 3, (it + 2) * 32);
        CP_COMMIT();

        const uint32_t sbase = sb + buf * SC_STG;
#pragma unroll
        for (int ks = 0; ks < 2; ks++) {
            uint32_t ah[2][4];
#pragma unroll
            for (int rf = 0; rf < 2; rf++)
                ldsm_x4(ah[rf], sbase + toff32(a_row + rf * 16, ks * 32 + a_kb));
#pragma unroll
            for (int ntp = 0; ntp < 4; ntp++) {
                uint32_t bh4[4];
                ldsm_x4(bh4, sbase + 8192 + toff32(b_row + ntp * 16, ks * 32 + b_kb));
#pragma unroll
                for (int rf = 0; rf < 2; rf++) {
                    mma16816h(acc[rf][2 * ntp],     ah[rf], bh4);
                    mma16816h(acc[rf][2 * ntp + 1], ah[rf], bh4 + 2);
                }
            }
        }
        buf++; if (buf == 3) buf = 0;
    }

    const int gID = lane >> 2, tig = lane & 3;
    const int mode = (z == 0) ? 0 : 1;
    char* smP = sm;
    float* rs_sm = (float*)(sm + 32768);
    float* kmS  = (float*)(sm + 33792);
    float* km2S = (float*)(sm + 34304);
    float* kvS  = (float*)(sm + 34816);
    float rs[2][2];
    rs[0][0] = rs[0][1] = rs[1][0] = rs[1][1] = 0.f;

    __syncthreads();
    if (mode == 1 && tid < 128) {
        float kmv = g.km[nBase + tid];
        float kvv = g.kv[nBase + tid];
        kmS[tid]  = kmv;
        km2S[tid] = kmv * kmv + 0.01f;
        kvS[tid]  = kvv + 0.03f;
    }
    __syncthreads();

#pragma unroll
    for (int rf = 0; rf < 2; rf++) {
        int r0 = mBase + wm * 32 + rf * 16 + gID;
        int r1 = r0 + 8;
        float qm0 = 0.f, qv0 = 0.f, qm1 = 0.f, qv1 = 0.f, qm0sq = 0.f, qm1sq = 0.f;
        if (mode == 1) {
            qm0 = g.qm[r0]; qv0 = g.qv[r0]; qm0sq = qm0 * qm0;
            qm1 = g.qm[r1]; qv1 = g.qv[r1]; qm1sq = qm1 * qm1;
        }
#pragma unroll
        for (int nt = 0; nt < 8; nt++) {
            int lcol = wn * 64 + nt * 8 + tig * 2;
            float v0 = acc[rf][nt][0], v1 = acc[rf][nt][1];
            float v2 = acc[rf][nt][2], v3 = acc[rf][nt][3];
            if (mode == 0) {
                v0 = __expf(v0 * 0.0625f); v1 = __expf(v1 * 0.0625f);
                v2 = __expf(v2 * 0.0625f); v3 = __expf(v3 * 0.0625f);
            } else {
                float km0 = kmS[lcol],  km20 = km2S[lcol],  kv0c = kvS[lcol];
                float km1 = kmS[lcol + 1], km21 = km2S[lcol + 1], kv1c = kvS[lcol + 1];
#define SSIMF(dot, QM, QMSQ, QV, KM, KM2, KVC)                                  \
    ({ float mp = (QM) * (KM);                                                  \
       float a = fmaf(2.f, mp, 0.01f);                                          \
       float t = fmaf((dot), 2.f / 255.f, fmaf(mp, -512.f / 255.f, 0.03f));     \
       float num = a * t;                                                       \
       float den = ((QMSQ) + (KM2)) * ((QV) + (KVC)) + 1e-8f;                   \
       __fdividef(num, den); })
                v0 = __expf(SSIMF(v0, qm0, qm0sq, qv0, km0, km20, kv0c));
                v1 = __expf(SSIMF(v1, qm0, qm0sq, qv0, km1, km21, kv1c));
                v2 = __expf(SSIMF(v2, qm1, qm1sq, qv1, km0, km20, kv0c));
                v3 = __expf(SSIMF(v3, qm1, qm1sq, qv1, km1, km21, kv1c));
            }
            rs[rf][0] += v0 + v1;
            rs[rf][1] += v2 + v3;

            int chunk = wn * 8 + nt;
            int rl0 = wm * 32 + rf * 16 + gID;
            int rl1 = rl0 + 8;
            __half2 p0; p0.x = __float2half(v0); p0.y = __float2half(v1);
            __half2 p1; p1.x = __float2half(v2); p1.y = __float2half(v3);
            uint32_t a0 = rl0 * 256 + ((chunk ^ (rl0 & 15)) << 4) + tig * 4;
            uint32_t a1 = rl1 * 256 + ((chunk ^ (rl1 & 15)) << 4) + tig * 4;
            *(__half2*)(smP + a0) = p0;
            *(__half2*)(smP + a1) = p1;
        }
    }

#pragma unroll
    for (int rf = 0; rf < 2; rf++)
#pragma unroll
        for (int h = 0; h < 2; h++) {
            rs[rf][h] += __shfl_xor_sync(0xffffffffu, rs[rf][h], 1);
            rs[rf][h] += __shfl_xor_sync(0xffffffffu, rs[rf][h], 2);
        }
    __syncthreads();
    if (tig == 0) {
#pragma unroll
        for (int rf = 0; rf < 2; rf++)
#pragma unroll
            for (int h = 0; h < 2; h++)
                rs_sm[wn * 128 + wm * 32 + rf * 16 + h * 8 + gID] = rs[rf][h];
    }
    __syncthreads();

    h16* __restrict__ P = g.P[z];
#pragma unroll
    for (int it = 0; it < 8; it++) {
        int idx = it * 256 + tid;
        int r = idx >> 4, c = idx & 15;
        uint32_t src = r * 256 + ((c ^ (r & 15)) << 4);
        size_t dst = (size_t)(mBase + r) * 2048 + nBase + c * 8;
        *(uint4*)(P + dst) = *(uint4*)(smP + src);
    }
    if (tid < 128)
        g.psum[z][(size_t)(mBase + tid) * 16 + blockIdx.y] = rs_sm[tid] + rs_sm[128 + tid];
}

// ---------------- PV GEMM: both branches fused, writes final out ----------------
struct PVArgs {
    const h16 *P0, *Vtc, *P1, *Vtf;
    const float *ps0, *ps1;
    float* out;
};

__global__ __launch_bounds__(256, 2) void pv_gemm(PVArgs g) {
    extern __shared__ char sm[];
    const uint32_t sb = smem_u32(sm);
    const int tid = threadIdx.x;
    const int wid = tid >> 5, lane = tid & 31;
    const int wm = wid & 3, wn = wid >> 2;
    const int mBase = blockIdx.x * 128;
    const int nBase = blockIdx.y * 128;

    float* li0 = (float*)(sm + 3 * TILE_STG);
    float* li1 = li0 + 128;
    {
        int r = tid & 127;
        const float* p = ((tid < 128) ? g.ps0 : g.ps1) + (size_t)(mBase + r) * 16;
        float s = 0.f;
#pragma unroll
        for (int i = 0; i < 16; i++) s += p[i];
        ((tid < 128) ? li0 : li1)[r] = 1.f / s;
    }
    __syncthreads();

    MMA_DECL();
    MMA_RUN64(g.P0, g.Vtc, 2048);

    // scale branch-0 acc by li0/li1 (so final *li1 yields li0*acc0 + li1*acc1)
    const int gID = lane >> 2;
    const int tig = lane & 3;
#pragma unroll
    for (int rf = 0; rf < 2; rf++) {
        int rl0 = wm * 32 + rf * 16 + gID;
        int rl1 = rl0 + 8;
        float t0 = __fdividef(li0[rl0], li1[rl0]);
        float t1 = __fdividef(li0[rl1], li1[rl1]);
#pragma unroll
        for (int nt = 0; nt < 8; nt++) {
            acc[rf][nt][0] *= t0; acc[rf][nt][1] *= t0;
            acc[rf][nt][2] *= t1; acc[rf][nt][3] *= t1;
        }
    }
    __syncthreads();   // all warps done reading stage buffers before branch-1 refill

    MMA_RUN64(g.P1, g.Vtf, 2048);

    float* __restrict__ C = g.out;
#pragma unroll
    for (int rf = 0; rf < 2; rf++) {
        int rl0 = wm * 32 + rf * 16 + gID;
        int rl1 = rl0 + 8;
        int r0 = mBase + rl0, r1 = mBase + rl1;
        float i0 = li1[rl0], i1 = li1[rl1];
#pragma unroll
        for (int nt = 0; nt < 8; nt++) {
            int col = nBase + wn * 64 + nt * 8 + tig * 2;
            *(float2*)(C + (size_t)r0 * 256 + col) =
                make_float2(acc[rf][nt][0] * i0, acc[rf][nt][1] * i0);
            *(float2*)(C + (size_t)r1 * 256 + col) =
                make_float2(acc[rf][nt][2] * i1, acc[rf][nt][3] * i1);
        }
    }
}

// ---------------- launch ----------------
extern "C" void kernel_launch(void* const* d_in, const int* in_sizes, int n_in,
                              void* d_out, int out_size) {
    const float* x    = (const float*)d_in[0];
    const float* chm  = (const float*)d_in[1];
    const float* chwq = (const float*)d_in[2];
    const float* chwk = (const float*)d_in[3];
    const float* chwv = (const float*)d_in[4];
    const float* spm  = (const float*)d_in[5];
    const float* spwq = (const float*)d_in[6];
    const float* spwk = (const float*)d_in[7];
    const float* spwv = (const float*)d_in[8];
    float* out = (float*)d_out;

    h16 *xh, *cmh, *smh, *wh;
    h16 *Qc, *Qf, *Kc, *Kf, *Vtc, *Vtf, *P0, *P1;
    float *ps0, *ps1, *qm, *qv, *km, *kv;
    cudaGetSymbolAddress((void**)&xh, g_x);
    cudaGetSymbolAddress((void**)&cmh, g_cm);
    cudaGetSymbolAddress((void**)&smh, g_sm2);
    cudaGetSymbolAddress((void**)&wh, g_w);
    cudaGetSymbolAddress((void**)&Qc, g_Qc);      cudaGetSymbolAddress((void**)&Qf, g_Qf);
    cudaGetSymbolAddress((void**)&Kc, g_Kc);      cudaGetSymbolAddress((void**)&Kf, g_Kf);
    cudaGetSymbolAddress((void**)&Vtc, g_Vtc);    cudaGetSymbolAddress((void**)&Vtf, g_Vtf);
    cudaGetSymbolAddress((void**)&P0, g_P0);      cudaGetSymbolAddress((void**)&P1, g_P1);
    cudaGetSymbolAddress((void**)&ps0, g_psum0);  cudaGetSymbolAddress((void**)&ps1, g_psum1);
    cudaGetSymbolAddress((void**)&qm, g_qm);      cudaGetSymbolAddress((void**)&qv, g_qv);
    cudaGetSymbolAddress((void**)&km, g_km);      cudaGetSymbolAddress((void**)&kv, g_kv);

    cudaFuncSetAttribute(mma_gemm, cudaFuncAttributeMaxDynamicSharedMemorySize, SC_SMEM);
    cudaFuncSetAttribute(mma_proj, cudaFuncAttributeMaxDynamicSharedMemorySize, GEMM_SMEM);
    cudaFuncSetAttribute(pv_gemm, cudaFuncAttributeMaxDynamicSharedMemorySize, PV_SMEM);

    // 0: fp32 -> fp16
    const int WSZ = DDIM * DDIM;
    ConvArgs cv;
    cv.src[0] = x;    cv.dst[0] = xh;           cv.nblk[0] = NB * DDIM / 1024;
    cv.src[1] = chm;  cv.dst[1] = cmh;          cv.nblk[1] = MTOT * DDIM / 1024;
    cv.src[2] = spm;  cv.dst[2] = smh;          cv.nblk[2] = MTOT * DDIM / 1024;
    cv.src[3] = spwq; cv.dst[3] = wh + 0 * WSZ; cv.nblk[3] = WSZ / 1024;
    cv.src[4] = chwq; cv.dst[4] = wh + 1 * WSZ; cv.nblk[4] = WSZ / 1024;
    cv.src[5] = spwk; cv.dst[5] = wh + 2 * WSZ; cv.nblk[5] = WSZ / 1024;
    cv.src[6] = chwk; cv.dst[6] = wh + 3 * WSZ; cv.nblk[6] = WSZ / 1024;
    cv.src[7] = chwv; cv.dst[7] = wh + 4 * WSZ; cv.nblk[7] = WSZ / 1024;
    cv.src[8] = spwv; cv.dst[8] = wh + 5 * WSZ; cv.nblk[8] = WSZ / 1024;
    int totBlk = 0;
    for (int i = 0; i < 9; i++) totBlk += cv.nblk[i];
    conv_all<<<totBlk, 256>>>(cv);

    // 1: projections
    ProjM pm;
    pm.A_[0] = xh;  pm.B_[0] = wh + 0 * WSZ; pm.O[0] = Qf;  pm.mx[0] = NB / 128;   pm.trans[0] = 0;
    pm.A_[1] = xh;  pm.B_[1] = wh + 1 * WSZ; pm.O[1] = Qc;  pm.mx[1] = NB / 128;   pm.trans[1] = 0;
    pm.A_[2] = smh; pm.B_[2] = wh + 2 * WSZ; pm.O[2] = Kf;  pm.mx[2] = MTOT / 128; pm.trans[2] = 0;
    pm.A_[3] = cmh; pm.B_[3] = wh + 3 * WSZ; pm.O[3] = Kc;  pm.mx[3] = MTOT / 128; pm.trans[3] = 0;
    pm.A_[4] = cmh; pm.B_[4] = wh + 4 * WSZ; pm.O[4] = Vtc; pm.mx[4] = MTOT / 128; pm.trans[4] = 1;
    pm.A_[5] = smh; pm.B_[5] = wh + 5 * WSZ; pm.O[5] = Vtf; pm.mx[5] = MTOT / 128; pm.trans[5] = 1;
    mma_proj<<<dim3(NB / 128, 2, 6), 256, GEMM_SMEM>>>(pm);

    // 2: row stats
    row_stats2<<<(NB + MTOT) / 8, 256>>>(Qf, Kf, qm, qv, km, kv);

    // 3: score GEMMs (profiled)
    MMArgs sa;
    sa.A_[0] = Qc; sa.B_[0] = Kc;
    sa.A_[1] = Qf; sa.B_[1] = Kf;
    sa.P[0] = P0; sa.P[1] = P1;
    sa.psum[0] = ps0; sa.psum[1] = ps1;
    sa.qm = qm; sa.qv = qv; sa.km = km; sa.kv = kv;
    mma_gemm<<<dim3(NB / 128, MTOT / 128, 2), 256, SC_SMEM>>>(sa);

    // 4: PV both branches fused -> final out
    PVArgs pa;
    pa.P0 = P0; pa.Vtc = Vtc; pa.P1 = P1; pa.Vtf = Vtf;
    pa.ps0 = ps0; pa.ps1 = ps1;
    pa.out = out;
    pv_gemm<<<dim3(NB / 128, DDIM / 128), 256, PV_SMEM>>>(pa);
}

// round 15
// speedup vs baseline: 1.0763x; 1.0763x over previous
#include <cuda_runtime.h>
#include <cuda_fp16.h>
#include <cstdint>

#define NB   12544
#define MTOT 2048
#define DDIM 256

typedef __half h16;

// ---------------- scratch ----------------
__device__ __align__(16) h16 g_x[NB * DDIM];
__device__ __align__(16) h16 g_cm[MTOT * DDIM];
__device__ __align__(16) h16 g_sm2[MTOT * DDIM];
__device__ __align__(16) h16 g_w[6 * DDIM * DDIM];
__device__ __align__(16) h16 g_Qc[NB * DDIM];
__device__ __align__(16) h16 g_Qf[NB * DDIM];
__device__ __align__(16) h16 g_Kc[MTOT * DDIM];
__device__ __align__(16) h16 g_Kf[MTOT * DDIM];
__device__ __align__(16) h16 g_Vtc[DDIM * MTOT];
__device__ __align__(16) h16 g_Vtf[DDIM * MTOT];
__device__ __align__(16) h16 g_P0[(size_t)NB * MTOT];
__device__ __align__(16) h16 g_P1[(size_t)NB * MTOT];
__device__ float g_psum0[NB * 16], g_psum1[NB * 16];
__device__ float g_linv0[NB], g_linv1[NB];
__device__ float g_qm[NB], g_qv[NB], g_km[MTOT], g_kv[MTOT];
__device__ float g_OutS[NB * DDIM];

// ---------------- helpers ----------------
__device__ __forceinline__ uint32_t smem_u32(const void* p) {
    uint32_t a;
    asm("{ .reg .u64 t; cvta.to.shared.u64 t, %1; cvt.u32.u64 %0, t; }" : "=r"(a) : "l"(p));
    return a;
}
#define SWZ(o) ((o) ^ (((o) >> 3) & 0x70))

__device__ __forceinline__ void mma16816h(float* c, const uint32_t* a, const uint32_t* b) {
    asm volatile(
        "mma.sync.aligned.m16n8k16.row.col.f32.f16.f16.f32 "
        "{%0,%1,%2,%3}, {%4,%5,%6,%7}, {%8,%9}, {%0,%1,%2,%3};"
        : "+f"(c[0]), "+f"(c[1]), "+f"(c[2]), "+f"(c[3])
        : "r"(a[0]), "r"(a[1]), "r"(a[2]), "r"(a[3]), "r"(b[0]), "r"(b[1]));
}
__device__ __forceinline__ void ldsm_x4(uint32_t* r, uint32_t addr) {
    asm volatile("ldmatrix.sync.aligned.m8n8.x4.shared.b16 {%0,%1,%2,%3}, [%4];"
                 : "=r"(r[0]), "=r"(r[1]), "=r"(r[2]), "=r"(r[3]) : "r"(addr));
}
__device__ __forceinline__ void cp16(uint32_t dst, const void* src) {
    asm volatile("cp.async.cg.shared.global [%0], [%1], 16;" :: "r"(dst), "l"(src));
}
#define CP_COMMIT() asm volatile("cp.async.commit_group;" ::: "memory")
#define CP_WAIT1()  asm volatile("cp.async.wait_group 1;" ::: "memory")

// 32-K chunk packed tile: 128 rows x 64B -> 64 smem rows x 128B
__device__ __forceinline__ uint32_t toff32(int row, int cb) {
    return SWZ((uint32_t)((row & 63) * 128 + ((row >> 6) << 6) + cb));
}
// 64-K chunk full tile: 128 rows x 128B
__device__ __forceinline__ uint32_t toff64(int row, int cb) {
    return SWZ((uint32_t)(row * 128 + cb));
}

#define TILE_STG 32768
#define GEMM_SMEM (3 * TILE_STG)
#define SC_STG 16384
#define SC_SMEM (3 * SC_STG)

// ---------------- fp32 -> fp16 conversion (9 arrays) ----------------
struct ConvArgs {
    const float* src[9];
    h16* dst[9];
    int nblk[9];
};
__global__ __launch_bounds__(256) void conv_all(ConvArgs a) {
    int bx = blockIdx.x, z = 0;
    while (bx >= a.nblk[z]) { bx -= a.nblk[z]; z++; }
    size_t i = ((size_t)bx * 256 + threadIdx.x) * 4;
    float4 v = *(const float4*)(a.src[z] + i);
    __half2 ha; ha.x = __float2half(v.x); ha.y = __float2half(v.y);
    __half2 hb; hb.x = __float2half(v.z); hb.y = __float2half(v.w);
    *(__half2*)(a.dst[z] + i) = ha;
    *(__half2*)(a.dst[z] + i + 2) = hb;
}

// ---------------- 64-K chunk single-product fp16 mainloop ----------------
#define MMA_LOOP64()                                                            \
    float acc[2][8][4];                                                         \
    _Pragma("unroll")                                                           \
    for (int rf = 0; rf < 2; rf++)                                              \
        _Pragma("unroll")                                                       \
        for (int nt = 0; nt < 8; nt++)                                          \
            _Pragma("unroll")                                                   \
            for (int c = 0; c < 4; c++) acc[rf][nt][c] = 0.f;                   \
    const int a_row = wm * 32 + (lane & 15);                                    \
    const int a_kb  = (lane >> 4) * 16;                                         \
    const int b_row = wn * 64 + ((lane >> 4) << 3) + (lane & 7);                \
    const int b_kb  = ((lane >> 3) & 1) * 16;                                   \
    const int nIter = Klen >> 6;                                                \
    auto issue = [&](int buf_, int k0) {                                        \
        uint32_t base = sb + buf_ * TILE_STG;                                   \
        _Pragma("unroll")                                                       \
        for (int u = 0; u < 4; u++) {                                           \
            int idx = u * 256 + tid;                                            \
            int r = idx >> 3, gch = idx & 7;                                    \
            uint32_t off = SWZ((uint32_t)(r * 128 + gch * 16));                 \
            cp16(base + off,         A + (size_t)(mBase + r) * Klen + k0 + gch * 8); \
            cp16(base + 16384 + off, B + (size_t)(nBase + r) * Klen + k0 + gch * 8); \
        }                                                                       \
    };                                                                          \
    issue(0, 0); CP_COMMIT();                                                   \
    if (nIter > 1) issue(1, 64);                                                \
    CP_COMMIT();                                                                \
    int buf = 0;                                                                \
    for (int it = 0; it < nIter; it++) {                                        \
        CP_WAIT1();                                                             \
        __syncthreads();                                                        \
        if (it + 2 < nIter) issue((it + 2) % 3, (it + 2) * 64);                 \
        CP_COMMIT();                                                            \
        const uint32_t sbase = sb + buf * TILE_STG;                             \
        _Pragma("unroll")                                                       \
        for (int ks = 0; ks < 4; ks++) {                                        \
            uint32_t ah[2][4];                                                  \
            _Pragma("unroll")                                                   \
            for (int rf = 0; rf < 2; rf++)                                      \
                ldsm_x4(ah[rf], sbase + toff64(a_row + rf * 16, ks * 32 + a_kb)); \
            _Pragma("unroll")                                                   \
            for (int ntp = 0; ntp < 4; ntp++) {                                 \
                uint32_t bh4[4];                                                \
                ldsm_x4(bh4, sbase + 16384 + toff64(b_row + ntp * 16, ks * 32 + b_kb)); \
                _Pragma("unroll")                                               \
                for (int rf = 0; rf < 2; rf++) {                                \
                    mma16816h(acc[rf][2 * ntp],     ah[rf], bh4);               \
                    mma16816h(acc[rf][2 * ntp + 1], ah[rf], bh4 + 2);           \
                }                                                               \
            }                                                                   \
        }                                                                       \
        buf++; if (buf == 3) buf = 0;                                           \
    }

// ---------------- projection GEMMs (single-product fp16, 64-K) ----------------
struct ProjM {
    const h16 *A_[6], *B_[6];
    h16* O[6];
    int mx[6], trans[6];
};
__global__ __launch_bounds__(256, 2) void mma_proj(ProjM p) {
    extern __shared__ char sm[];
    const int z = blockIdx.z;
    if ((int)blockIdx.x >= p.mx[z]) return;
    const uint32_t sb = smem_u32(sm);
    const h16* __restrict__ A = p.A_[z];
    const h16* __restrict__ B = p.B_[z];
    const int Klen = 256;
    const int tid = threadIdx.x;
    const int wid = tid >> 5, lane = tid & 31;
    const int wm = wid & 3, wn = wid >> 2;
    const int mBase = blockIdx.x * 128;
    const int nBase = blockIdx.y * 128;

    MMA_LOOP64();

    const int gID = lane >> 2, tig = lane & 3;
    h16* __restrict__ O = p.O[z];
    __syncthreads();
    char* smP = sm;

    if (p.trans[z]) {
        // stage transposed [d_local(128)][m_local(128)] fp16, then coalesced STG
#pragma unroll
        for (int rf = 0; rf < 2; rf++) {
#pragma unroll
            for (int nt = 0; nt < 8; nt++) {
#pragma unroll
                for (int c = 0; c < 4; c++) {
                    int ml = wm * 32 + rf * 16 + (c >> 1) * 8 + gID;
                    int dl = wn * 64 + nt * 8 + tig * 2 + (c & 1);
                    uint32_t addr = dl * 256 + (((ml >> 3) ^ (dl & 15)) << 4) + (ml & 7) * 2;
                    *(h16*)(smP + addr) = __float2half(acc[rf][nt][c]);
                }
            }
        }
        __syncthreads();
#pragma unroll
        for (int it = 0; it < 8; it++) {
            int idx = it * 256 + tid;
            int d = idx >> 4, cch = idx & 15;
            uint32_t src = d * 256 + ((cch ^ (d & 15)) << 4);
            size_t dst = (size_t)(nBase + d) * MTOT + mBase + cch * 8;
            *(uint4*)(O + dst) = *(uint4*)(smP + src);
        }
        return;
    }

#pragma unroll
    for (int rf = 0; rf < 2; rf++) {
#pragma unroll
        for (int nt = 0; nt < 8; nt++) {
            int chunk = wn * 8 + nt;
#pragma unroll
            for (int half = 0; half < 2; half++) {
                int rl = wm * 32 + rf * 16 + half * 8 + gID;
                __half2 hh;
                hh.x = __float2half(acc[rf][nt][half * 2 + 0]);
                hh.y = __float2half(acc[rf][nt][half * 2 + 1]);
                uint32_t addr = rl * 256 + ((chunk ^ (rl & 15)) << 4) + tig * 4;
                *(__half2*)(smP + addr) = hh;
            }
        }
    }
    __syncthreads();
#pragma unroll
    for (int it = 0; it < 8; it++) {
        int idx = it * 256 + tid;
        int r = idx >> 4, c = idx & 15;
        uint32_t src = r * 256 + ((c ^ (r & 15)) << 4);
        size_t dst = (size_t)(mBase + r) * 256 + nBase + c * 8;
        *(uint4*)(O + dst) = *(uint4*)(smP + src);
    }
}

// ---------------- merged row stats (fp16 input) ----------------
__global__ __launch_bounds__(256) void row_stats2(
    const h16* __restrict__ Qf, const h16* __restrict__ Kf,
    float* __restrict__ qm, float* __restrict__ qv,
    float* __restrict__ km, float* __restrict__ kv) {
    int row = blockIdx.x * 8 + (threadIdx.x >> 5);
    const int lane = threadIdx.x & 31;
    const h16* X;
    float *mean, *var;
    if (row < NB) { X = Qf; mean = qm; var = qv; }
    else { row -= NB; X = Kf; mean = km; var = kv; }
    const size_t base = (size_t)row * 256;
    float s = 0.f, ss = 0.f;
#pragma unroll
    for (int c = 0; c < 256; c += 32) {
        float v = __half2float(X[base + c + lane]);
        s += v; ss += v * v;
    }
#pragma unroll
    for (int o = 16; o > 0; o >>= 1) {
        s += __shfl_xor_sync(0xffffffffu, s, o);
        ss += __shfl_xor_sync(0xffffffffu, ss, o);
    }
    if (lane == 0) {
        float m = s * (1.f / 256.f);
        mean[row] = m;
        var[row] = (ss - 256.f * m * m) * (1.f / 255.f);
    }
}

// ---------------- score MMA GEMM: single-product fp16, 32-K chunks ----------------
struct MMArgs {
    const h16 *A_[2], *B_[2];
    h16* P[2];
    float* psum[2];
    const float *qm, *qv, *km, *kv;
};

__global__ __launch_bounds__(256, 2) void mma_gemm(MMArgs g) {
    extern __shared__ char sm[];
    const uint32_t sb = smem_u32(sm);
    const int z = blockIdx.z;
    const h16* __restrict__ A = g.A_[z];
    const h16* __restrict__ B = g.B_[z];
    const int Klen = 256;
    const int tid = threadIdx.x;
    const int wid = tid >> 5, lane = tid & 31;
    const int wm = wid & 3, wn = wid >> 2;
    const int mBase = blockIdx.x * 128;
    const int nBase = blockIdx.y * 128;

    float acc[2][8][4];
#pragma unroll
    for (int rf = 0; rf < 2; rf++)
#pragma unroll
        for (int nt = 0; nt < 8; nt++)
#pragma unroll
            for (int c = 0; c < 4; c++) acc[rf][nt][c] = 0.f;

    const int a_row = wm * 32 + (lane & 15);
    const int a_kb  = (lane >> 4) * 16;
    const int b_row = wn * 64 + ((lane >> 4) << 3) + (lane & 7);
    const int b_kb  = ((lane >> 3) & 1) * 16;
    const int lr0 = tid >> 2;
    const int lg  = (tid & 3);
    const int nIter = Klen >> 5;

    auto issue = [&](int buf, int k0) {
        uint32_t base = sb + buf * SC_STG;
#pragma unroll
        for (int h = 0; h < 2; h++) {
            int r = lr0 + h * 64;
            uint32_t off = toff32(r, lg * 16);
            cp16(base + off,        A + (size_t)(mBase + r) * Klen + k0 + lg * 8);
            cp16(base + 8192 + off, B + (size_t)(nBase + r) * Klen + k0 + lg * 8);
        }
    };

    issue(0, 0); CP_COMMIT();
    issue(1, 32); CP_COMMIT();

    int buf = 0;
    for (int it = 0; it < nIter; it++) {
        CP_WAIT1();
        __syncthreads();
        if (it + 2 < nIter) issue((it + 2) % 3, (it + 2) * 32);
        CP_COMMIT();

        const uint32_t sbase = sb + buf * SC_STG;
#pragma unroll
        for (int ks = 0; ks < 2; ks++) {
            uint32_t ah[2][4];
#pragma unroll
            for (int rf = 0; rf < 2; rf++)
                ldsm_x4(ah[rf], sbase + toff32(a_row + rf * 16, ks * 32 + a_kb));
#pragma unroll
            for (int ntp = 0; ntp < 4; ntp++) {
                uint32_t bh4[4];
                ldsm_x4(bh4, sbase + 8192 + toff32(b_row + ntp * 16, ks * 32 + b_kb));
#pragma unroll
                for (int rf = 0; rf < 2; rf++) {
                    mma16816h(acc[rf][2 * ntp],     ah[rf], bh4);
                    mma16816h(acc[rf][2 * ntp + 1], ah[rf], bh4 + 2);
                }
            }
        }
        buf++; if (buf == 3) buf = 0;
    }

    const int gID = lane >> 2, tig = lane & 3;
    const int mode = (z == 0) ? 0 : 1;
    char* smP = sm;
    float* rs_sm = (float*)(sm + 32768);
    float* kmS  = (float*)(sm + 33792);
    float* km2S = (float*)(sm + 34304);
    float* kvS  = (float*)(sm + 34816);
    float rs[2][2];
    rs[0][0] = rs[0][1] = rs[1][0] = rs[1][1] = 0.f;

    __syncthreads();
    if (mode == 1 && tid < 128) {
        float kmv = g.km[nBase + tid];
        float kvv = g.kv[nBase + tid];
        kmS[tid]  = kmv;
        km2S[tid] = kmv * kmv + 0.01f;
        kvS[tid]  = kvv + 0.03f;
    }
    __syncthreads();

#pragma unroll
    for (int rf = 0; rf < 2; rf++) {
        int r0 = mBase + wm * 32 + rf * 16 + gID;
        int r1 = r0 + 8;
        float qm0 = 0.f, qv0 = 0.f, qm1 = 0.f, qv1 = 0.f, qm0sq = 0.f, qm1sq = 0.f;
        if (mode == 1) {
            qm0 = g.qm[r0]; qv0 = g.qv[r0]; qm0sq = qm0 * qm0;
            qm1 = g.qm[r1]; qv1 = g.qv[r1]; qm1sq = qm1 * qm1;
        }
#pragma unroll
        for (int nt = 0; nt < 8; nt++) {
            int lcol = wn * 64 + nt * 8 + tig * 2;
            float v0 = acc[rf][nt][0], v1 = acc[rf][nt][1];
            float v2 = acc[rf][nt][2], v3 = acc[rf][nt][3];
            if (mode == 0) {
                v0 = __expf(v0 * 0.0625f); v1 = __expf(v1 * 0.0625f);
                v2 = __expf(v2 * 0.0625f); v3 = __expf(v3 * 0.0625f);
            } else {
                float km0 = kmS[lcol],  km20 = km2S[lcol],  kv0c = kvS[lcol];
                float km1 = kmS[lcol + 1], km21 = km2S[lcol + 1], kv1c = kvS[lcol + 1];
#define SSIMF(dot, QM, QMSQ, QV, KM, KM2, KVC)                                  \
    ({ float mp = (QM) * (KM);                                                  \
       float a = fmaf(2.f, mp, 0.01f);                                          \
       float t = fmaf((dot), 2.f / 255.f, fmaf(mp, -512.f / 255.f, 0.03f));     \
       float num = a * t;                                                       \
       float den = ((QMSQ) + (KM2)) * ((QV) + (KVC)) + 1e-8f;                   \
       __fdividef(num, den); })
                v0 = __expf(SSIMF(v0, qm0, qm0sq, qv0, km0, km20, kv0c));
                v1 = __expf(SSIMF(v1, qm0, qm0sq, qv0, km1, km21, kv1c));
                v2 = __expf(SSIMF(v2, qm1, qm1sq, qv1, km0, km20, kv0c));
                v3 = __expf(SSIMF(v3, qm1, qm1sq, qv1, km1, km21, kv1c));
            }
            rs[rf][0] += v0 + v1;
            rs[rf][1] += v2 + v3;

            int chunk = wn * 8 + nt;
            int rl0 = wm * 32 + rf * 16 + gID;
            int rl1 = rl0 + 8;
            __half2 p0; p0.x = __float2half(v0); p0.y = __float2half(v1);
            __half2 p1; p1.x = __float2half(v2); p1.y = __float2half(v3);
            uint32_t a0 = rl0 * 256 + ((chunk ^ (rl0 & 15)) << 4) + tig * 4;
            uint32_t a1 = rl1 * 256 + ((chunk ^ (rl1 & 15)) << 4) + tig * 4;
            *(__half2*)(smP + a0) = p0;
            *(__half2*)(smP + a1) = p1;
        }
    }

#pragma unroll
    for (int rf = 0; rf < 2; rf++)
#pragma unroll
        for (int h = 0; h < 2; h++) {
            rs[rf][h] += __shfl_xor_sync(0xffffffffu, rs[rf][h], 1);
            rs[rf][h] += __shfl_xor_sync(0xffffffffu, rs[rf][h], 2);
        }
    __syncthreads();
    if (tig == 0) {
#pragma unroll
        for (int rf = 0; rf < 2; rf++)
#pragma unroll
            for (int h = 0; h < 2; h++)
                rs_sm[wn * 128 + wm * 32 + rf * 16 + h * 8 + gID] = rs[rf][h];
    }
    __syncthreads();

    h16* __restrict__ P = g.P[z];
#pragma unroll
    for (int it = 0; it < 8; it++) {
        int idx = it * 256 + tid;
        int r = idx >> 4, c = idx & 15;
        uint32_t src = r * 256 + ((c ^ (r & 15)) << 4);
        size_t dst = (size_t)(mBase + r) * 2048 + nBase + c * 8;
        *(uint4*)(P + dst) = *(uint4*)(smP + src);
    }
    if (tid < 128)
        g.psum[z][(size_t)(mBase + tid) * 16 + blockIdx.y] = rs_sm[tid] + rs_sm[128 + tid];
}

// ---------------- PV GEMM: single-product fp16, 64-K chunks ----------------
struct PVArgs {
    const h16 *A_[2], *B_[2];
    float* C[2];
    const float* linv[2];
};

__global__ __launch_bounds__(256, 2) void pv_gemm(PVArgs g) {
    extern __shared__ char sm[];
    const uint32_t sb = smem_u32(sm);
    const int z = blockIdx.z;
    const h16* __restrict__ A = g.A_[z];
    const h16* __restrict__ B = g.B_[z];
    const int Klen = 2048;
    const int tid = threadIdx.x;
    const int wid = tid >> 5, lane = tid & 31;
    const int wm = wid & 3, wn = wid >> 2;
    const int mBase = blockIdx.x * 128;
    const int nBase = blockIdx.y * 128;

    MMA_LOOP64();

    const int gID = lane >> 2, tig = lane & 3;
    float* __restrict__ C = g.C[z];
    const float* __restrict__ linv = g.linv[z];
#pragma unroll
    for (int rf = 0; rf < 2; rf++) {
        int r0 = mBase + wm * 32 + rf * 16 + gID;
        int r1 = r0 + 8;
        float i0 = linv[r0], i1 = linv[r1];
#pragma unroll
        for (int nt = 0; nt < 8; nt++) {
            int col = nBase + wn * 64 + nt * 8 + tig * 2;
            *(float2*)(C + (size_t)r0 * 256 + col) =
                make_float2(acc[rf][nt][0] * i0, acc[rf][nt][1] * i0);
            *(float2*)(C + (size_t)r1 * 256 + col) =
                make_float2(acc[rf][nt][2] * i1, acc[rf][nt][3] * i1);
        }
    }
}

// ---------------- reduce partial sums -> 1/l ----------------
__global__ __launch_bounds__(256) void reduce_l2(const float* __restrict__ ps0,
                                                 const float* __restrict__ ps1,
                                                 float* __restrict__ li0,
                                                 float* __restrict__ li1) {
    int row = blockIdx.x * 256 + threadIdx.x;
    const float* p = (blockIdx.y == 0 ? ps0 : ps1) + (size_t)row * 16;
    float s = 0.f;
#pragma unroll
    for (int i = 0; i < 16; i++) s += p[i];
    (blockIdx.y == 0 ? li0 : li1)[row] = 1.f / s;
}

// ---------------- out += outS ----------------
__global__ __launch_bounds__(256) void add_out(float* __restrict__ out,
                                               const float* __restrict__ add) {
    int i = (blockIdx.x * 256 + threadIdx.x) * 4;
    float4 a = *(float4*)(out + i);
    float4 b = *(const float4*)(add + i);
    a.x += b.x; a.y += b.y; a.z += b.z; a.w += b.w;
    *(float4*)(out + i) = a;
}

// ---------------- launch ----------------
extern "C" void kernel_launch(void* const* d_in, const int* in_sizes, int n_in,
                              void* d_out, int out_size) {
    const float* x    = (const float*)d_in[0];
    const float* chm  = (const float*)d_in[1];
    const float* chwq = (const float*)d_in[2];
    const float* chwk = (const float*)d_in[3];
    const float* chwv = (const float*)d_in[4];
    const float* spm  = (const float*)d_in[5];
    const float* spwq = (const float*)d_in[6];
    const float* spwk = (const float*)d_in[7];
    const float* spwv = (const float*)d_in[8];
    float* out = (float*)d_out;

    h16 *xh, *cmh, *smh, *wh;
    h16 *Qc, *Qf, *Kc, *Kf, *Vtc, *Vtf, *P0, *P1;
    float *ps0, *ps1, *li0, *li1, *qm, *qv, *km, *kv, *outS;
    cudaGetSymbolAddress((void**)&xh, g_x);
    cudaGetSymbolAddress((void**)&cmh, g_cm);
    cudaGetSymbolAddress((void**)&smh, g_sm2);
    cudaGetSymbolAddress((void**)&wh, g_w);
    cudaGetSymbolAddress((void**)&Qc, g_Qc);      cudaGetSymbolAddress((void**)&Qf, g_Qf);
    cudaGetSymbolAddress((void**)&Kc, g_Kc);      cudaGetSymbolAddress((void**)&Kf, g_Kf);
    cudaGetSymbolAddress((void**)&Vtc, g_Vtc);    cudaGetSymbolAddress((void**)&Vtf, g_Vtf);
    cudaGetSymbolAddress((void**)&P0, g_P0);      cudaGetSymbolAddress((void**)&P1, g_P1);
    cudaGetSymbolAddress((void**)&ps0, g_psum0);  cudaGetSymbolAddress((void**)&ps1, g_psum1);
    cudaGetSymbolAddress((void**)&li0, g_linv0);  cudaGetSymbolAddress((void**)&li1, g_linv1);
    cudaGetSymbolAddress((void**)&qm, g_qm);      cudaGetSymbolAddress((void**)&qv, g_qv);
    cudaGetSymbolAddress((void**)&km, g_km);      cudaGetSymbolAddress((void**)&kv, g_kv);
    cudaGetSymbolAddress((void**)&outS, g_OutS);

    cudaFuncSetAttribute(mma_gemm, cudaFuncAttributeMaxDynamicSharedMemorySize, SC_SMEM);
    cudaFuncSetAttribute(mma_proj, cudaFuncAttributeMaxDynamicSharedMemorySize, GEMM_SMEM);
    cudaFuncSetAttribute(pv_gemm, cudaFuncAttributeMaxDynamicSharedMemorySize, GEMM_SMEM);

    // 0: fp32 -> fp16
    const int WSZ = DDIM * DDIM;
    ConvArgs cv;
    cv.src[0] = x;    cv.dst[0] = xh;           cv.nblk[0] = NB * DDIM / 1024;
    cv.src[1] = chm;  cv.dst[1] = cmh;          cv.nblk[1] = MTOT * DDIM / 1024;
    cv.src[2] = spm;  cv.dst[2] = smh;          cv.nblk[2] = MTOT * DDIM / 1024;
    cv.src[3] = spwq; cv.dst[3] = wh + 0 * WSZ; cv.nblk[3] = WSZ / 1024;
    cv.src[4] = chwq; cv.dst[4] = wh + 1 * WSZ; cv.nblk[4] = WSZ / 1024;
    cv.src[5] = spwk; cv.dst[5] = wh + 2 * WSZ; cv.nblk[5] = WSZ / 1024;
    cv.src[6] = chwk; cv.dst[6] = wh + 3 * WSZ; cv.nblk[6] = WSZ / 1024;
    cv.src[7] = chwv; cv.dst[7] = wh + 4 * WSZ; cv.nblk[7] = WSZ / 1024;
    cv.src[8] = spwv; cv.dst[8] = wh + 5 * WSZ; cv.nblk[8] = WSZ / 1024;
    int totBlk = 0;
    for (int i = 0; i < 9; i++) totBlk += cv.nblk[i];
    conv_all<<<totBlk, 256>>>(cv);

    // 1: projections
    ProjM pm;
    pm.A_[0] = xh;  pm.B_[0] = wh + 0 * WSZ; pm.O[0] = Qf;  pm.mx[0] = NB / 128;   pm.trans[0] = 0;
    pm.A_[1] = xh;  pm.B_[1] = wh + 1 * WSZ; pm.O[1] = Qc;  pm.mx[1] = NB / 128;   pm.trans[1] = 0;
    pm.A_[2] = smh; pm.B_[2] = wh + 2 * WSZ; pm.O[2] = Kf;  pm.mx[2] = MTOT / 128; pm.trans[2] = 0;
    pm.A_[3] = cmh; pm.B_[3] = wh + 3 * WSZ; pm.O[3] = Kc;  pm.mx[3] = MTOT / 128; pm.trans[3] = 0;
    pm.A_[4] = cmh; pm.B_[4] = wh + 4 * WSZ; pm.O[4] = Vtc; pm.mx[4] = MTOT / 128; pm.trans[4] = 1;
    pm.A_[5] = smh; pm.B_[5] = wh + 5 * WSZ; pm.O[5] = Vtf; pm.mx[5] = MTOT / 128; pm.trans[5] = 1;
    mma_proj<<<dim3(NB / 128, 2, 6), 256, GEMM_SMEM>>>(pm);

    // 2: row stats
    row_stats2<<<(NB + MTOT) / 8, 256>>>(Qf, Kf, qm, qv, km, kv);

    // 3: score GEMMs (profiled)
    MMArgs sa;
    sa.A_[0] = Qc; sa.B_[0] = Kc;
    sa.A_[1] = Qf; sa.B_[1] = Kf;
    sa.P[0] = P0; sa.P[1] = P1;
    sa.psum[0] = ps0; sa.psum[1] = ps1;
    sa.qm = qm; sa.qv = qv; sa.km = km; sa.kv = kv;
    mma_gemm<<<dim3(NB / 128, MTOT / 128, 2), 256, SC_SMEM>>>(sa);

    // 4: reduce
    reduce_l2<<<dim3(NB / 256, 2), 256>>>(ps0, ps1, li0, li1);

    // 5: PV GEMMs
    PVArgs pa;
    pa.A_[0] = P0; pa.B_[0] = Vtc; pa.C[0] = out;  pa.linv[0] = li0;
    pa.A_[1] = P1; pa.B_[1] = Vtf; pa.C[1] = outS; pa.linv[1] = li1;
    pv_gemm<<<dim3(NB / 128, DDIM / 128, 2), 256, GEMM_SMEM>>>(pa);

    // 6: combine
    add_out<<<NB * DDIM / 1024, 256>>>(out, outS);
}